// round 3
// baseline (speedup 1.0000x reference)
#include <cuda_runtime.h>
#include <math_constants.h>

#define Bsz 2048
#define Dd 16
#define Ff 512
#define LOG2E_F 1.4426950408889634f
#define LN2_F 0.6931471805599453f
#define LOG2PI_F 1.8378770664093453f

// Scratch (no allocations allowed in kernel_launch)
__device__ float g_pk[Bsz * 48];   // per (j,d): A, B, C' (quadratic form coeffs, log2-domain, Lconst folded in)
__device__ float g_arr0[Bsz];      // log_q_zx[i] - log_prior[i]
__device__ float g_lqz[Bsz];       // log q(z)
__device__ float g_lqzp[Bsz];      // log prod_d q(z_d)
__device__ float g_part[256];      // recon partial sums

__device__ __forceinline__ float ex2f(float x) {
    float y; asm("ex2.approx.ftz.f32 %0, %1;" : "=f"(y) : "f"(x)); return y;
}
__device__ __forceinline__ float lg2f_(float x) {
    float y; asm("lg2.approx.f32 %0, %1;" : "=f"(y) : "f"(x)); return y;
}

// ---------------------------------------------------------------------------
// K1: precompute per-(j,d) quadratic coefficients in log2 domain.
// gld(z | mu_j, lv_j) * LOG2E = a*z^2 + b*z + c   with
//   a = -0.5*LOG2E*exp(-lv), b = -2*a*mu, c = a*mu^2 - 0.5*LOG2E*(lv+LOG2PI)
// We fold Lconst = -log2(M) (the default importance weight) into c.
// ---------------------------------------------------------------------------
__global__ void k_pre(const float* __restrict__ mu, const float* __restrict__ lv) {
    int idx = blockIdx.x * blockDim.x + threadIdx.x;
    if (idx >= Bsz * Dd) return;
    int j = idx >> 4, d = idx & 15;
    float m = mu[idx], v = lv[idx];
    float a = -0.5f * LOG2E_F * ex2f(-v * LOG2E_F);
    float off = -0.5f * LOG2E_F * (v + LOG2PI_F);
    float Lc = -lg2f_(2047.0f);
    g_pk[j * 48 + d]      = a;
    g_pk[j * 48 + 16 + d] = -2.0f * a * m;
    g_pk[j * 48 + 32 + d] = fmaf(a * m, m, off) + Lc;
}

// ---------------------------------------------------------------------------
// K1b: per-i log q(z|x) - log p(z)  (both tiny [B,D] sums)
// ---------------------------------------------------------------------------
__global__ void k_peri(const float* __restrict__ z, const float* __restrict__ mu,
                       const float* __restrict__ lv) {
    int i = blockIdx.x * blockDim.x + threadIdx.x;
    if (i >= Bsz) return;
    float acc = 0.f, sz2 = 0.f;
#pragma unroll
    for (int d = 0; d < Dd; d++) {
        float zd = z[i * Dd + d];
        float md = mu[i * Dd + d];
        float vd = lv[i * Dd + d];
        float t = zd - md;
        acc += -0.5f * (t * t * ex2f(-vd * LOG2E_F) + vd + LOG2PI_F);
        sz2 = fmaf(zd, zd, sz2);
    }
    // log p(z) with the reference's quirk: log_var = ones -> inv_sigma = e^-1
    float lprior = -0.5f * (sz2 * 0.36787944117144233f + 16.0f * (1.0f + LOG2PI_F));
    g_arr0[i] = acc - lprior;
}

// ---------------------------------------------------------------------------
// K2: reconstruction MAE partial sums (deterministic: fixed per-block order)
// ---------------------------------------------------------------------------
__global__ void k_recon(const float* __restrict__ x, const float* __restrict__ r) {
    __shared__ float sh[256];
    float acc = 0.f;
    const float4* x4 = (const float4*)x;
    const float4* r4 = (const float4*)r;
    const int n4 = (Bsz * Ff) / 4;
    for (int k = blockIdx.x * 256 + threadIdx.x; k < n4; k += 256 * 256) {
        float4 a = x4[k], b = r4[k];
        acc += fabsf(a.x - b.x) + fabsf(a.y - b.y) + fabsf(a.z - b.z) + fabsf(a.w - b.w);
    }
    sh[threadIdx.x] = acc;
    __syncthreads();
#pragma unroll
    for (int o = 128; o > 0; o >>= 1) {
        if (threadIdx.x < o) sh[threadIdx.x] += sh[threadIdx.x + o];
        __syncthreads();
    }
    if (threadIdx.x == 0) g_part[blockIdx.x] = sh[0];
}

// ---------------------------------------------------------------------------
// K3: main pairwise kernel. One warp per row i; lane owns j = lane + 32t.
// 17 online-logsumexp accumulators per lane (16 per-dim + 1 row), log2 domain.
// Branchless single-EX2 online update:
//   mn = max(m,u); e = exp2(-|u-m|); s = (u>m) ? s*e + 1 : s + e
// ---------------------------------------------------------------------------
__global__ void __launch_bounds__(128) k_main(const float* __restrict__ z,
                                              const int* __restrict__ nds) {
    const int lane = threadIdx.x & 31;
    const int i = blockIdx.x * 4 + (threadIdx.x >> 5);

    float zv[16];
    {
        const float4* zp = (const float4*)(z + i * Dd);
#pragma unroll
        for (int k = 0; k < 4; k++) {
            float4 v = zp[k];
            zv[4 * k] = v.x; zv[4 * k + 1] = v.y; zv[4 * k + 2] = v.z; zv[4 * k + 3] = v.w;
        }
    }

    const float Nf = (float)(*nds);
    const float Lc = -lg2f_(2047.0f);
    const float L0 = -lg2f_(Nf);
    const float L1 = lg2f_((Nf - 2047.0f) / (Nf * 2047.0f));
    // Importance-weight special columns (j=0 and j=1), plus W[B-2,0] override.
    float Lfirst = Lc;
    if (lane == 0) Lfirst = (i == Bsz - 2) ? L1 : L0;
    if (lane == 1) Lfirst = L1;
    const float dL = Lfirst - Lc;   // correction for tile 0 only

    float m[17], s[17];
#pragma unroll
    for (int k = 0; k < 17; k++) { m[k] = -CUDART_INF_F; s[k] = 0.f; }

    for (int t = 0; t < 64; t++) {
        const float4* p = (const float4*)(g_pk + (size_t)(t * 32 + lane) * 48);
        float ld[48];
#pragma unroll
        for (int k = 0; k < 12; k++) {
            float4 v = p[k];
            ld[4 * k] = v.x; ld[4 * k + 1] = v.y; ld[4 * k + 2] = v.z; ld[4 * k + 3] = v.w;
        }
        float Lt = Lc;
        if (t == 0) {   // warp-uniform branch, executes once
            Lt = Lfirst;
#pragma unroll
            for (int d = 0; d < 16; d++) ld[32 + d] += dL;
        }

        float S = 0.f;
#pragma unroll
        for (int d = 0; d < 16; d++) {
            // u = gld(z_i,d | j)*LOG2E + L2(j)   (weight folded into C)
            float u = fmaf(zv[d], fmaf(zv[d], ld[d], ld[16 + d]), ld[32 + d]);
            S += u;
            float md = m[d];
            float mn = fmaxf(md, u);
            float e = ex2f(-fabsf(u - md));
            bool gt = u > md;
            s[d] = fmaf(s[d], gt ? e : 1.0f, gt ? 1.0f : e);
            m[d] = mn;
        }
        // Row term: r = sum_d g + L2 = S - 15*L2
        float r = fmaf(-15.0f, Lt, S);
        {
            float md = m[16];
            float mn = fmaxf(md, r);
            float e = ex2f(-fabsf(r - md));
            bool gt = r > md;
            s[16] = fmaf(s[16], gt ? e : 1.0f, gt ? 1.0f : e);
            m[16] = mn;
        }
    }

    // Warp butterfly merge of (m, s) pairs
#pragma unroll
    for (int k = 0; k < 17; k++) {
#pragma unroll
        for (int o = 16; o > 0; o >>= 1) {
            float m2 = __shfl_xor_sync(0xffffffffu, m[k], o);
            float s2 = __shfl_xor_sync(0xffffffffu, s[k], o);
            float mn = fmaxf(m[k], m2);
            s[k] = s[k] * ex2f(m[k] - mn) + s2 * ex2f(m2 - mn);
            m[k] = mn;
        }
    }

    if (lane == 0) {
        float qz = LN2_F * (m[16] + lg2f_(s[16]));
        float qzp = 0.f;
#pragma unroll
        for (int d = 0; d < 16; d++) qzp += m[d] + lg2f_(s[d]);
        qzp *= LN2_F;
        g_lqz[i] = qz;
        g_lqzp[i] = qzp;
    }
}

// ---------------------------------------------------------------------------
// K4: final deterministic combine.
// total = recon + mean(lqzx) + 3*mean(lqz) - 3*mean(lqzp) - mean(lprior)
//       = recon_sum/(B*F) + (arr0_sum + 3*lqz_sum - 3*lqzp_sum)/B
// ---------------------------------------------------------------------------
__global__ void k_final(float* __restrict__ out) {
    __shared__ float sh[256];
    int t = threadIdx.x;
    float c = 0.f;
    for (int k = t; k < Bsz; k += 256)
        c += g_arr0[k] + 3.f * g_lqz[k] - 3.f * g_lqzp[k];
    float rp = g_part[t];

    sh[t] = c;
    __syncthreads();
#pragma unroll
    for (int o = 128; o > 0; o >>= 1) {
        if (t < o) sh[t] += sh[t + o];
        __syncthreads();
    }
    float ctot = sh[0];
    __syncthreads();
    sh[t] = rp;
    __syncthreads();
#pragma unroll
    for (int o = 128; o > 0; o >>= 1) {
        if (t < o) sh[t] += sh[t + o];
        __syncthreads();
    }
    if (t == 0)
        out[0] = sh[0] / (float)(Bsz * Ff) + ctot / (float)Bsz;
}

extern "C" void kernel_launch(void* const* d_in, const int* in_sizes, int n_in,
                              void* d_out, int out_size) {
    const float* x   = (const float*)d_in[0];
    const float* rec = (const float*)d_in[1];
    const float* mu  = (const float*)d_in[2];
    const float* lv  = (const float*)d_in[3];
    const float* z   = (const float*)d_in[4];
    const int*   nds = (const int*)d_in[5];
    float* out = (float*)d_out;

    k_pre<<<(Bsz * Dd + 255) / 256, 256>>>(mu, lv);
    k_peri<<<(Bsz + 255) / 256, 256>>>(z, mu, lv);
    k_recon<<<256, 256>>>(x, rec);
    k_main<<<Bsz / 4, 128>>>(z, nds);
    k_final<<<1, 256>>>(out);
}

// round 5
// speedup vs baseline: 1.9619x; 1.9619x over previous
#include <cuda_runtime.h>
#include <math_constants.h>

#define Bsz 2048
#define Dd 16
#define Ff 512
#define LOG2E_F 1.4426950408889634f
#define LN2_F 0.6931471805599453f
#define LOG2PI_F 1.8378770664093453f

typedef unsigned long long ull;

// Coefficient store: for dim-pair dp(0..7), type t(a,b,c): float2[2048] over j,
// element j = {coef(2dp)[j], coef(2dp+1)[j]}. Scalar float index:
//   ((dp*3+t)*2048 + j)*2 + (d&1)
__device__ float g_pk2f[24 * 2048 * 2];   // 393 KB, L2-resident
__device__ float g_bound[16];             // per-dim vertex upper bound (log2 units)
__device__ float g_arr0[Bsz];             // log q(z|x) - log p(z)
__device__ float g_lqz[Bsz];              // lg2(srow)  (relative, log2 units)
__device__ float g_lqzp[Bsz];             // sum_d lg2(s_d)
__device__ float g_part[256];             // recon partials

__device__ __forceinline__ float ex2f(float x) {
    float y; asm("ex2.approx.ftz.f32 %0, %1;" : "=f"(y) : "f"(x)); return y;
}
__device__ __forceinline__ float lg2f_(float x) {
    float y; asm("lg2.approx.f32 %0, %1;" : "=f"(y) : "f"(x)); return y;
}
__device__ __forceinline__ ull fma2_(ull a, ull b, ull c) {
    ull d; asm("fma.rn.f32x2 %0, %1, %2, %3;" : "=l"(d) : "l"(a), "l"(b), "l"(c)); return d;
}
__device__ __forceinline__ ull add2_(ull a, ull b) {
    ull d; asm("add.rn.f32x2 %0, %1, %2;" : "=l"(d) : "l"(a), "l"(b)); return d;
}
__device__ __forceinline__ void unpk(ull v, float& lo, float& hi) {
    asm("mov.b64 {%0, %1}, %2;" : "=f"(lo), "=f"(hi) : "l"(v));
}
__device__ __forceinline__ ull pk2(float lo, float hi) {
    ull v; asm("mov.b64 %0, {%1, %2};" : "=l"(v) : "f"(lo), "f"(hi)); return v;
}

// ---------------------------------------------------------------------------
// K0: per-dim vertex bound: maxterm_d = -0.5*LOG2E*(min_j lv[j,d] + LOG2PI)
// (vertex value of the log-density quadratic is independent of mu)
// ---------------------------------------------------------------------------
__global__ void k_bound(const float* __restrict__ lv) {
    __shared__ float sm[512];
    int t = threadIdx.x;
    int d = t & 15, ch = t >> 4;           // 32 chunks of 64 rows
    float mn = CUDART_INF_F;
    for (int r = ch; r < Bsz; r += 32) mn = fminf(mn, lv[r * Dd + d]);
    sm[t] = mn;
    __syncthreads();
#pragma unroll
    for (int off = 256; off >= 16; off >>= 1) {
        if (t < off) sm[t] = fminf(sm[t], sm[t + off]);
        __syncthreads();
    }
    if (t < 16) g_bound[t] = -0.5f * LOG2E_F * (sm[t] + LOG2PI_F);
}

// ---------------------------------------------------------------------------
// K1: coefficients, log2 domain, bound-shifted, j-major packed by dim pairs.
// u'(i,j,d) = a*z^2 + b*z + c' <= 0, with importance-weight deltas for j=0,1
// folded into c' (exact for per-dim LSE; row LSE corrected in k_main).
// ---------------------------------------------------------------------------
__global__ void k_pre(const float* __restrict__ mu, const float* __restrict__ lv,
                      const int* __restrict__ nds) {
    int idx = blockIdx.x * blockDim.x + threadIdx.x;
    if (idx >= Bsz * Dd) return;
    int j = idx >> 4, d = idx & 15;
    float m = mu[idx], v = lv[idx];
    float a = -0.5f * LOG2E_F * ex2f(-v * LOG2E_F);
    float off = -0.5f * LOG2E_F * (v + LOG2PI_F);
    float b = -2.0f * a * m;
    float c = fmaf(a * m, m, off) - g_bound[d];
    if (j < 2) {
        float Nf = (float)(*nds);
        float dL0 = lg2f_(2047.0f / Nf);               // L0 - Lc
        float dL1 = lg2f_((Nf - 2047.0f) / Nf);        // L1 - Lc
        c += (j == 0) ? dL0 : dL1;
    }
    int dp = d >> 1, h = d & 1;
    int e = j * 2 + h;
    g_pk2f[(dp * 3 + 0) * 4096 + e] = a;
    g_pk2f[(dp * 3 + 1) * 4096 + e] = b;
    g_pk2f[(dp * 3 + 2) * 4096 + e] = c;
}

// ---------------------------------------------------------------------------
// K1b: per-i log q(z|x) - log p(z)
// ---------------------------------------------------------------------------
__global__ void k_peri(const float* __restrict__ z, const float* __restrict__ mu,
                       const float* __restrict__ lv) {
    int i = blockIdx.x * blockDim.x + threadIdx.x;
    if (i >= Bsz) return;
    float acc = 0.f, sz2 = 0.f;
#pragma unroll
    for (int d = 0; d < Dd; d++) {
        float zd = z[i * Dd + d];
        float md = mu[i * Dd + d];
        float vd = lv[i * Dd + d];
        float t = zd - md;
        acc += -0.5f * (t * t * ex2f(-vd * LOG2E_F) + vd + LOG2PI_F);
        sz2 = fmaf(zd, zd, sz2);
    }
    float lprior = -0.5f * (sz2 * 0.36787944117144233f + 16.0f * (1.0f + LOG2PI_F));
    g_arr0[i] = acc - lprior;
}

// ---------------------------------------------------------------------------
// K2: reconstruction MAE partials
// ---------------------------------------------------------------------------
__global__ void k_recon(const float* __restrict__ x, const float* __restrict__ r) {
    __shared__ float sh[256];
    float acc = 0.f;
    const float4* x4 = (const float4*)x;
    const float4* r4 = (const float4*)r;
    const int n4 = (Bsz * Ff) / 4;
    for (int k = blockIdx.x * 256 + threadIdx.x; k < n4; k += 256 * 256) {
        float4 a = x4[k], b = r4[k];
        acc += fabsf(a.x - b.x) + fabsf(a.y - b.y) + fabsf(a.z - b.z) + fabsf(a.w - b.w);
    }
    sh[threadIdx.x] = acc;
    __syncthreads();
#pragma unroll
    for (int o = 128; o > 0; o >>= 1) {
        if (threadIdx.x < o) sh[threadIdx.x] += sh[threadIdx.x + o];
        __syncthreads();
    }
    if (threadIdx.x == 0) g_part[blockIdx.x] = sh[0];
}

// ---------------------------------------------------------------------------
// K3: main pairwise kernel. Warp handles rows {2w, 2w+1}; lane owns 4
// consecutive j's per tile (j = 4*lane + 128*t) -> fully coalesced
// ulonglong2 (=f32x2 pair) loads. No online max; plain exp2-accumulate.
// ---------------------------------------------------------------------------
__global__ void __launch_bounds__(128) k_main(const float* __restrict__ z,
                                              const int* __restrict__ nds) {
    const int lane = threadIdx.x & 31;
    const int w = blockIdx.x * 4 + (threadIdx.x >> 5);
    const int i0 = 2 * w, i1 = i0 + 1;

    ull zp0[8], zp1[8];
    {
        const float4* zq = (const float4*)(z + (size_t)i0 * Dd);
#pragma unroll
        for (int k = 0; k < 4; k++) {
            float4 v = zq[k];
            zp0[2 * k] = pk2(v.x, v.y); zp0[2 * k + 1] = pk2(v.z, v.w);
        }
        const float4* zq1 = (const float4*)(z + (size_t)i1 * Dd);
#pragma unroll
        for (int k = 0; k < 4; k++) {
            float4 v = zq1[k];
            zp1[2 * k] = pk2(v.x, v.y); zp1[2 * k + 1] = pk2(v.z, v.w);
        }
    }

    float s0[16], s1[16], srow0 = 0.f, srow1 = 0.f;
#pragma unroll
    for (int d = 0; d < 16; d++) { s0[d] = 0.f; s1[d] = 0.f; }

    const ulonglong2* pk = (const ulonglong2*)g_pk2f;

#pragma unroll 1
    for (int t = 0; t < 16; t++) {
        const int jh = 2 * lane + 64 * t;     // ulonglong2 index (covers j, j+1)
        ull S20[4], S21[4];
#pragma unroll
        for (int jj = 0; jj < 4; jj++) { S20[jj] = 0ull; S21[jj] = 0ull; }

#pragma unroll
        for (int dp = 0; dp < 8; dp++) {
            ulonglong2 A0 = pk[(dp * 3 + 0) * 1024 + jh];
            ulonglong2 A1 = pk[(dp * 3 + 0) * 1024 + jh + 1];
            ulonglong2 B0 = pk[(dp * 3 + 1) * 1024 + jh];
            ulonglong2 B1 = pk[(dp * 3 + 1) * 1024 + jh + 1];
            ulonglong2 C0 = pk[(dp * 3 + 2) * 1024 + jh];
            ulonglong2 C1 = pk[(dp * 3 + 2) * 1024 + jh + 1];
            ull av[4] = {A0.x, A0.y, A1.x, A1.y};
            ull bv[4] = {B0.x, B0.y, B1.x, B1.y};
            ull cv[4] = {C0.x, C0.y, C1.x, C1.y};
#pragma unroll
            for (int jj = 0; jj < 4; jj++) {
                ull u = fma2_(zp0[dp], fma2_(zp0[dp], av[jj], bv[jj]), cv[jj]);
                float ul, uh; unpk(u, ul, uh);
                s0[2 * dp]     += ex2f(ul);
                s0[2 * dp + 1] += ex2f(uh);
                S20[jj] = add2_(S20[jj], u);

                ull u1 = fma2_(zp1[dp], fma2_(zp1[dp], av[jj], bv[jj]), cv[jj]);
                unpk(u1, ul, uh);
                s1[2 * dp]     += ex2f(ul);
                s1[2 * dp + 1] += ex2f(uh);
                S21[jj] = add2_(S21[jj], u1);
            }
        }
#pragma unroll
        for (int jj = 0; jj < 4; jj++) {
            float l, h;
            unpk(S20[jj], l, h); srow0 += ex2f(l + h);
            unpk(S21[jj], l, h); srow1 += ex2f(l + h);
        }
    }

    // ---- post-loop exact corrections (lane 0 owns j=0 and j=1 partials) ----
    if (lane == 0) {
        float Nf = (float)(*nds);
        float dL0 = lg2f_(2047.0f / Nf);
        float dL1 = lg2f_((Nf - 2047.0f) / Nf);
        float S0_0 = 0.f, S1_0 = 0.f, S0_1 = 0.f, S1_1 = 0.f;
        float u0d0[16];
#pragma unroll
        for (int dp = 0; dp < 8; dp++) {
            ulonglong2 A = pk[(dp * 3 + 0) * 1024];
            ulonglong2 B = pk[(dp * 3 + 1) * 1024];
            ulonglong2 C = pk[(dp * 3 + 2) * 1024];
            float l, h;
            ull u0 = fma2_(zp0[dp], fma2_(zp0[dp], A.x, B.x), C.x);
            unpk(u0, l, h); S0_0 += l + h; u0d0[2 * dp] = l; u0d0[2 * dp + 1] = h;
            ull u1 = fma2_(zp0[dp], fma2_(zp0[dp], A.y, B.y), C.y);
            unpk(u1, l, h); S1_0 += l + h;
            ull v0 = fma2_(zp1[dp], fma2_(zp1[dp], A.x, B.x), C.x);
            unpk(v0, l, h); S0_1 += l + h;
            ull v1 = fma2_(zp1[dp], fma2_(zp1[dp], A.y, B.y), C.y);
            unpk(v1, l, h); S1_1 += l + h;
        }
        // row-sum corrections: loop over-applied 16*dL_j; want 1*dL_j(i).
        float c00 = (i0 == Bsz - 2) ? (dL1 - 16.f * dL0) : (-15.f * dL0);
        float c01 = -15.f * dL0;                  // i1 is odd, never B-2
        float c1  = -15.f * dL1;
        srow0 += (ex2f(c00) - 1.f) * ex2f(S0_0) + (ex2f(c1) - 1.f) * ex2f(S1_0);
        srow1 += (ex2f(c01) - 1.f) * ex2f(S0_1) + (ex2f(c1) - 1.f) * ex2f(S1_1);
        // W[B-2, 0] override for the per-dim sums (only row B-2, which is even)
        if (i0 == Bsz - 2) {
            float wfix = ex2f(dL1 - dL0) - 1.f;
#pragma unroll
            for (int d = 0; d < 16; d++) s0[d] += wfix * ex2f(u0d0[d]);
        }
    }

    // ---- plain-sum butterfly (shared offsets => no max merging) ----
#pragma unroll
    for (int off = 16; off > 0; off >>= 1) {
#pragma unroll
        for (int d = 0; d < 16; d++) {
            s0[d] += __shfl_xor_sync(0xffffffffu, s0[d], off);
            s1[d] += __shfl_xor_sync(0xffffffffu, s1[d], off);
        }
        srow0 += __shfl_xor_sync(0xffffffffu, srow0, off);
        srow1 += __shfl_xor_sync(0xffffffffu, srow1, off);
    }

    if (lane == 0) {
        g_lqz[i0] = lg2f_(srow0);
        g_lqz[i1] = lg2f_(srow1);
        float p0 = 0.f, p1 = 0.f;
#pragma unroll
        for (int d = 0; d < 16; d++) { p0 += lg2f_(s0[d]); p1 += lg2f_(s1[d]); }
        g_lqzp[i0] = p0;
        g_lqzp[i1] = p1;
    }
}

// ---------------------------------------------------------------------------
// K4: final combine.
// total = recon_mean + mean(arr0) + 3*mean(lqz - lqzp)
// with lqz - lqzp = LN2*(lg2srow - sum_lg2s) + LN2*(-15*Lc); -15*Lc = 15*log2(2047)
// => constant 3*15*ln(2047) = 45*ln(2047).
// ---------------------------------------------------------------------------
__global__ void k_final(float* __restrict__ out) {
    __shared__ float sh[256];
    int t = threadIdx.x;
    float c = 0.f;
    for (int k = t; k < Bsz; k += 256)
        c += g_arr0[k] + 3.f * LN2_F * (g_lqz[k] - g_lqzp[k]);
    float rp = g_part[t];

    sh[t] = c;
    __syncthreads();
#pragma unroll
    for (int o = 128; o > 0; o >>= 1) {
        if (t < o) sh[t] += sh[t + o];
        __syncthreads();
    }
    float ctot = sh[0];
    __syncthreads();
    sh[t] = rp;
    __syncthreads();
#pragma unroll
    for (int o = 128; o > 0; o >>= 1) {
        if (t < o) sh[t] += sh[t + o];
        __syncthreads();
    }
    if (t == 0)
        out[0] = sh[0] / (float)(Bsz * Ff) + ctot / (float)Bsz
               + 45.0f * logf(2047.0f);
}

extern "C" void kernel_launch(void* const* d_in, const int* in_sizes, int n_in,
                              void* d_out, int out_size) {
    const float* x   = (const float*)d_in[0];
    const float* rec = (const float*)d_in[1];
    const float* mu  = (const float*)d_in[2];
    const float* lv  = (const float*)d_in[3];
    const float* z   = (const float*)d_in[4];
    const int*   nds = (const int*)d_in[5];
    float* out = (float*)d_out;

    k_bound<<<1, 512>>>(lv);
    k_pre<<<(Bsz * Dd + 255) / 256, 256>>>(mu, lv, nds);
    k_peri<<<(Bsz + 255) / 256, 256>>>(z, mu, lv);
    k_recon<<<256, 256>>>(x, rec);
    k_main<<<Bsz / 8, 128>>>(z, nds);
    k_final<<<1, 256>>>(out);
}

// round 6
// speedup vs baseline: 3.1356x; 1.5982x over previous
#include <cuda_runtime.h>
#include <math_constants.h>

#define Bsz 2048
#define Dd 16
#define Ff 512
#define LOG2E_F 1.4426950408889634f
#define LN2_F 0.6931471805599453f
#define LOG2PI_F 1.8378770664093453f

typedef unsigned long long ull;

// Coefficient store: segment s = dp*3 + type (dp=dim-pair 0..7, type a/b/c),
// each segment is float2[2048] over j: float2[j] = {coef_{2dp}[j], coef_{2dp+1}[j]}
__device__ float g_pk2f[24 * 2048 * 2];   // 393 KB
__device__ float g_arr0[Bsz];             // log q(z|x) - log p(z)
__device__ float g_lqz[Bsz];              // lg2(srow)
__device__ float g_lqzp[Bsz];             // sum_d lg2(s_d)
__device__ float g_part[512];             // recon partials

__device__ __forceinline__ float ex2f(float x) {
    float y; asm("ex2.approx.ftz.f32 %0, %1;" : "=f"(y) : "f"(x)); return y;
}
__device__ __forceinline__ float lg2f_(float x) {
    float y; asm("lg2.approx.f32 %0, %1;" : "=f"(y) : "f"(x)); return y;
}
__device__ __forceinline__ ull fma2_(ull a, ull b, ull c) {
    ull d; asm("fma.rn.f32x2 %0, %1, %2, %3;" : "=l"(d) : "l"(a), "l"(b), "l"(c)); return d;
}
__device__ __forceinline__ ull add2_(ull a, ull b) {
    ull d; asm("add.rn.f32x2 %0, %1, %2;" : "=l"(d) : "l"(a), "l"(b)); return d;
}
__device__ __forceinline__ void unpk(ull v, float& lo, float& hi) {
    asm("mov.b64 {%0, %1}, %2;" : "=f"(lo), "=f"(hi) : "l"(v));
}
__device__ __forceinline__ ull pk2(float lo, float hi) {
    ull v; asm("mov.b64 %0, {%1, %2};" : "=l"(v) : "f"(lo), "f"(hi)); return v;
}

// ---------------------------------------------------------------------------
// K_prep: blocks [0,128): coefficients (j-major, dim-pair packed, log2 domain,
//         j=0/1 importance-weight deltas folded into c).
//         blocks [128,136): per-i  log q(z|x) - log p(z).
// No bound shift needed: u <= ~+0.5 for any sane lv, exp2 cannot overflow.
// ---------------------------------------------------------------------------
__global__ void k_prep(const float* __restrict__ mu, const float* __restrict__ lv,
                       const float* __restrict__ z, const int* __restrict__ nds) {
    int b = blockIdx.x;
    if (b < 128) {
        int idx = b * 256 + threadIdx.x;          // exactly 32768 = Bsz*Dd
        int j = idx >> 4, d = idx & 15;
        float m = mu[idx], v = lv[idx];
        float a = -0.5f * LOG2E_F * ex2f(-v * LOG2E_F);
        float off = -0.5f * LOG2E_F * (v + LOG2PI_F);
        float bb = -2.0f * a * m;
        float c = fmaf(a * m, m, off);
        if (j < 2) {
            float Nf = (float)(*nds);
            float dL0 = lg2f_(2047.0f / Nf);
            float dL1 = lg2f_((Nf - 2047.0f) / Nf);
            c += (j == 0) ? dL0 : dL1;
        }
        int dp = d >> 1, h = d & 1;
        int e = j * 2 + h;
        g_pk2f[(dp * 3 + 0) * 4096 + e] = a;
        g_pk2f[(dp * 3 + 1) * 4096 + e] = bb;
        g_pk2f[(dp * 3 + 2) * 4096 + e] = c;
    } else {
        int i = (b - 128) * 256 + threadIdx.x;    // exactly 2048
        float acc = 0.f, sz2 = 0.f;
#pragma unroll
        for (int d = 0; d < Dd; d++) {
            float zd = z[i * Dd + d];
            float md = mu[i * Dd + d];
            float vd = lv[i * Dd + d];
            float t = zd - md;
            acc += -0.5f * (t * t * ex2f(-vd * LOG2E_F) + vd + LOG2PI_F);
            sz2 = fmaf(zd, zd, sz2);
        }
        float lprior = -0.5f * (sz2 * 0.36787944117144233f + 16.0f * (1.0f + LOG2PI_F));
        g_arr0[i] = acc - lprior;
    }
}

// ---------------------------------------------------------------------------
// K_main: 128 blocks x 256 threads (8 warps). Warp w handles rows
// {16*blk + 2w, +1}. Coefficients staged per-block into smem in 64-j tiles
// (double buffered, reg-prefetch), so each block reads the 393KB array from
// L2 exactly once (50MB chip-wide). Lane owns j-pair 2*lane(+64t); all
// accumulation is plain exp2-add (weights pre-folded; exact corrections for
// the j=0/1 columns applied post-loop by lane 0).
// ---------------------------------------------------------------------------
__global__ void __launch_bounds__(256) k_main(const float* __restrict__ z,
                                              const int* __restrict__ nds) {
    __shared__ float4 sbuf[2][768];               // 24 segments x 32 float4
    const int tid = threadIdx.x;
    const int lane = tid & 31;
    const int w = tid >> 5;
    const int i0 = blockIdx.x * 16 + 2 * w, i1 = i0 + 1;

    ull zp0[8], zp1[8];
    {
        const float4* zq = (const float4*)(z + (size_t)i0 * Dd);
#pragma unroll
        for (int k = 0; k < 4; k++) {
            float4 v = zq[k];
            zp0[2 * k] = pk2(v.x, v.y); zp0[2 * k + 1] = pk2(v.z, v.w);
        }
        const float4* zq1 = (const float4*)(z + (size_t)i1 * Dd);
#pragma unroll
        for (int k = 0; k < 4; k++) {
            float4 v = zq1[k];
            zp1[2 * k] = pk2(v.x, v.y); zp1[2 * k + 1] = pk2(v.z, v.w);
        }
    }

    float s0[16], s1[16], srow0 = 0.f, srow1 = 0.f;
#pragma unroll
    for (int d = 0; d < 16; d++) { s0[d] = 0.f; s1[d] = 0.f; }

    const float4* gp4 = (const float4*)g_pk2f;
    const int es = tid >> 5 == tid >> 5 ? 0 : 0;  // (no-op; keep compiler calm)
    (void)es;

    // prologue: stage tile 0
    {
        float4 pf[3];
#pragma unroll
        for (int k = 0; k < 3; k++) {
            int e = tid + k * 256; int s = e >> 5, q = e & 31;
            pf[k] = gp4[s * 1024 + q];
        }
#pragma unroll
        for (int k = 0; k < 3; k++) {
            int e = tid + k * 256; int s = e >> 5, q = e & 31;
            sbuf[0][s * 32 + q] = pf[k];
        }
    }
    __syncthreads();

#pragma unroll 1
    for (int t = 0; t < 32; t++) {
        float4 pf[3];
        if (t < 31) {
#pragma unroll
            for (int k = 0; k < 3; k++) {
                int e = tid + k * 256; int s = e >> 5, q = e & 31;
                pf[k] = gp4[s * 1024 + 32 * (t + 1) + q];
            }
        }

        const ulonglong2* sb2 = (const ulonglong2*)sbuf[t & 1];
        ull SR00 = 0ull, SR01 = 0ull, SR10 = 0ull, SR11 = 0ull;

#pragma unroll
        for (int dp = 0; dp < 8; dp++) {
            ulonglong2 A = sb2[(dp * 3 + 0) * 32 + lane];
            ulonglong2 B = sb2[(dp * 3 + 1) * 32 + lane];
            ulonglong2 C = sb2[(dp * 3 + 2) * 32 + lane];
            float l, h;
            // row 0, j
            ull u = fma2_(zp0[dp], fma2_(zp0[dp], A.x, B.x), C.x);
            unpk(u, l, h); s0[2 * dp] += ex2f(l); s0[2 * dp + 1] += ex2f(h);
            SR00 = add2_(SR00, u);
            // row 0, j+1
            u = fma2_(zp0[dp], fma2_(zp0[dp], A.y, B.y), C.y);
            unpk(u, l, h); s0[2 * dp] += ex2f(l); s0[2 * dp + 1] += ex2f(h);
            SR01 = add2_(SR01, u);
            // row 1, j
            u = fma2_(zp1[dp], fma2_(zp1[dp], A.x, B.x), C.x);
            unpk(u, l, h); s1[2 * dp] += ex2f(l); s1[2 * dp + 1] += ex2f(h);
            SR10 = add2_(SR10, u);
            // row 1, j+1
            u = fma2_(zp1[dp], fma2_(zp1[dp], A.y, B.y), C.y);
            unpk(u, l, h); s1[2 * dp] += ex2f(l); s1[2 * dp + 1] += ex2f(h);
            SR11 = add2_(SR11, u);
        }
        {
            float l, h;
            unpk(SR00, l, h); srow0 += ex2f(l + h);
            unpk(SR01, l, h); srow0 += ex2f(l + h);
            unpk(SR10, l, h); srow1 += ex2f(l + h);
            unpk(SR11, l, h); srow1 += ex2f(l + h);
        }

        if (t < 31) {
#pragma unroll
            for (int k = 0; k < 3; k++) {
                int e = tid + k * 256; int s = e >> 5, q = e & 31;
                sbuf[(t + 1) & 1][s * 32 + q] = pf[k];
            }
        }
        __syncthreads();
    }

    // ---- post-loop exact corrections (lane 0 owns j=0 and j=1) ----
    const ulonglong2* pk = (const ulonglong2*)g_pk2f;
    if (lane == 0) {
        float Nf = (float)(*nds);
        float dL0 = lg2f_(2047.0f / Nf);
        float dL1 = lg2f_((Nf - 2047.0f) / Nf);
        float S0_0 = 0.f, S1_0 = 0.f, S0_1 = 0.f, S1_1 = 0.f;
        float u0d0[16];
#pragma unroll
        for (int dp = 0; dp < 8; dp++) {
            ulonglong2 A = pk[(dp * 3 + 0) * 1024];
            ulonglong2 B = pk[(dp * 3 + 1) * 1024];
            ulonglong2 C = pk[(dp * 3 + 2) * 1024];
            float l, h;
            ull u0 = fma2_(zp0[dp], fma2_(zp0[dp], A.x, B.x), C.x);
            unpk(u0, l, h); S0_0 += l + h; u0d0[2 * dp] = l; u0d0[2 * dp + 1] = h;
            ull u1 = fma2_(zp0[dp], fma2_(zp0[dp], A.y, B.y), C.y);
            unpk(u1, l, h); S1_0 += l + h;
            ull v0 = fma2_(zp1[dp], fma2_(zp1[dp], A.x, B.x), C.x);
            unpk(v0, l, h); S0_1 += l + h;
            ull v1 = fma2_(zp1[dp], fma2_(zp1[dp], A.y, B.y), C.y);
            unpk(v1, l, h); S1_1 += l + h;
        }
        // row-sum: loop applied 16*dL_j; true weight is 1*dL_j(row).
        float c00 = (i0 == Bsz - 2) ? (dL1 - 16.f * dL0) : (-15.f * dL0);
        float c01 = -15.f * dL0;                  // odd rows are never B-2
        float c1  = -15.f * dL1;
        srow0 += (ex2f(c00) - 1.f) * ex2f(S0_0) + (ex2f(c1) - 1.f) * ex2f(S1_0);
        srow1 += (ex2f(c01) - 1.f) * ex2f(S0_1) + (ex2f(c1) - 1.f) * ex2f(S1_1);
        // W[B-2, 0] per-dim override (row B-2 is even -> row i0)
        if (i0 == Bsz - 2) {
            float wfix = ex2f(dL1 - dL0) - 1.f;
#pragma unroll
            for (int d = 0; d < 16; d++) s0[d] += wfix * ex2f(u0d0[d]);
        }
    }

    // ---- plain-sum butterfly ----
#pragma unroll
    for (int off = 16; off > 0; off >>= 1) {
#pragma unroll
        for (int d = 0; d < 16; d++) {
            s0[d] += __shfl_xor_sync(0xffffffffu, s0[d], off);
            s1[d] += __shfl_xor_sync(0xffffffffu, s1[d], off);
        }
        srow0 += __shfl_xor_sync(0xffffffffu, srow0, off);
        srow1 += __shfl_xor_sync(0xffffffffu, srow1, off);
    }

    if (lane == 0) {
        g_lqz[i0] = lg2f_(srow0);
        g_lqz[i1] = lg2f_(srow1);
        float p0 = 0.f, p1 = 0.f;
#pragma unroll
        for (int d = 0; d < 16; d++) { p0 += lg2f_(s0[d]); p1 += lg2f_(s1[d]); }
        g_lqzp[i0] = p0;
        g_lqzp[i1] = p1;
    }
}

// ---------------------------------------------------------------------------
// K_recon: MAE partials, 512 blocks (each thread exactly 2 float4 pairs)
// ---------------------------------------------------------------------------
__global__ void k_recon(const float* __restrict__ x, const float* __restrict__ r) {
    __shared__ float sh[256];
    float acc = 0.f;
    const float4* x4 = (const float4*)x;
    const float4* r4 = (const float4*)r;
    const int n4 = (Bsz * Ff) / 4;
    for (int k = blockIdx.x * 256 + threadIdx.x; k < n4; k += 512 * 256) {
        float4 a = x4[k], b = r4[k];
        acc += fabsf(a.x - b.x) + fabsf(a.y - b.y) + fabsf(a.z - b.z) + fabsf(a.w - b.w);
    }
    sh[threadIdx.x] = acc;
    __syncthreads();
#pragma unroll
    for (int o = 128; o > 0; o >>= 1) {
        if (threadIdx.x < o) sh[threadIdx.x] += sh[threadIdx.x + o];
        __syncthreads();
    }
    if (threadIdx.x == 0) g_part[blockIdx.x] = sh[0];
}

// ---------------------------------------------------------------------------
// K_final: total = recon_mean + mean(arr0) + 3*ln2*mean(lg2srow - sum_lg2s)
//          + 45*ln(2047)   (the -15*Lc row-weight constant, x3)
// ---------------------------------------------------------------------------
__global__ void k_final(float* __restrict__ out) {
    __shared__ float sh[256];
    int t = threadIdx.x;
    float c = 0.f;
    for (int k = t; k < Bsz; k += 256)
        c += g_arr0[k] + 3.f * LN2_F * (g_lqz[k] - g_lqzp[k]);
    float rp = g_part[t] + g_part[t + 256];

    sh[t] = c;
    __syncthreads();
#pragma unroll
    for (int o = 128; o > 0; o >>= 1) {
        if (t < o) sh[t] += sh[t + o];
        __syncthreads();
    }
    float ctot = sh[0];
    __syncthreads();
    sh[t] = rp;
    __syncthreads();
#pragma unroll
    for (int o = 128; o > 0; o >>= 1) {
        if (t < o) sh[t] += sh[t + o];
        __syncthreads();
    }
    if (t == 0)
        out[0] = sh[0] / (float)(Bsz * Ff) + ctot / (float)Bsz
               + 45.0f * logf(2047.0f);
}

extern "C" void kernel_launch(void* const* d_in, const int* in_sizes, int n_in,
                              void* d_out, int out_size) {
    const float* x   = (const float*)d_in[0];
    const float* rec = (const float*)d_in[1];
    const float* mu  = (const float*)d_in[2];
    const float* lv  = (const float*)d_in[3];
    const float* z   = (const float*)d_in[4];
    const int*   nds = (const int*)d_in[5];
    float* out = (float*)d_out;

    k_prep<<<136, 256>>>(mu, lv, z, nds);
    k_main<<<128, 256>>>(z, nds);        // position 1 mod 4 -> ncu -s 5 lands here
    k_recon<<<512, 256>>>(x, rec);
    k_final<<<1, 256>>>(out);
}